// round 3
// baseline (speedup 1.0000x reference)
#include <cuda_runtime.h>
#include <math.h>

// Problem constants
#define M_ROWS   4096     // B*T
#define T_SEQ    2048
#define D_MODEL  2048
#define KV_D     512
#define HEAD_DIM 128
#define N_HEADS  16
#define N_KV     4
#define GRP      4        // H / HKV

// ---------------- scratch (one device global; no allocations allowed) ------
// layout: q [M*D] | k [M*KVD] | v [M*KVD] | attn [M*D]
#define OFF_Q    0
#define OFF_K    (M_ROWS * D_MODEL)
#define OFF_V    (OFF_K + M_ROWS * KV_D)
#define OFF_ATTN (OFF_V + M_ROWS * KV_D)
#define SCRATCH_FLOATS (OFF_ATTN + M_ROWS * D_MODEL)
__device__ float g_scratch[SCRATCH_FLOATS];

// ======================= GEMM: C[M,N] = A[M,K] * B[N,K]^T ==================
// A row-major [M,K], B row-major [N,K] (K-major both sides -> NT GEMM).
#define GBM 128
#define GBN 128
#define GBK 16
#define AST 132   // padded smem row stride (floats), keeps float4 alignment

__global__ __launch_bounds__(256)
void gemm_nt(const float* __restrict__ A, const float* __restrict__ B,
             float* __restrict__ C, int N, int K) {
    __shared__ float As[GBK][AST];
    __shared__ float Bs[GBK][AST];
    int tid = threadIdx.x;
    int tx = tid & 15, ty = tid >> 4;

    const float* Ab = A + (size_t)blockIdx.y * GBM * K;
    const float* Bb = B + (size_t)blockIdx.x * GBN * K;

    float acc[8][8];
#pragma unroll
    for (int i = 0; i < 8; i++)
#pragma unroll
        for (int j = 0; j < 8; j++) acc[i][j] = 0.f;

    int lr = tid >> 1;          // 0..127 : tile row
    int lk = (tid & 1) * 8;     // 0 or 8 : k offset

    for (int k0 = 0; k0 < K; k0 += GBK) {
        float4 a0 = *(const float4*)(Ab + (size_t)lr * K + k0 + lk);
        float4 a1 = *(const float4*)(Ab + (size_t)lr * K + k0 + lk + 4);
        float4 b0 = *(const float4*)(Bb + (size_t)lr * K + k0 + lk);
        float4 b1 = *(const float4*)(Bb + (size_t)lr * K + k0 + lk + 4);

        As[lk + 0][lr] = a0.x; As[lk + 1][lr] = a0.y;
        As[lk + 2][lr] = a0.z; As[lk + 3][lr] = a0.w;
        As[lk + 4][lr] = a1.x; As[lk + 5][lr] = a1.y;
        As[lk + 6][lr] = a1.z; As[lk + 7][lr] = a1.w;
        Bs[lk + 0][lr] = b0.x; Bs[lk + 1][lr] = b0.y;
        Bs[lk + 2][lr] = b0.z; Bs[lk + 3][lr] = b0.w;
        Bs[lk + 4][lr] = b1.x; Bs[lk + 5][lr] = b1.y;
        Bs[lk + 6][lr] = b1.z; Bs[lk + 7][lr] = b1.w;
        __syncthreads();

#pragma unroll
        for (int kk = 0; kk < GBK; kk++) {
            float a[8], b[8];
            *(float4*)&a[0] = *(const float4*)&As[kk][ty * 4];
            *(float4*)&a[4] = *(const float4*)&As[kk][64 + ty * 4];
            *(float4*)&b[0] = *(const float4*)&Bs[kk][tx * 4];
            *(float4*)&b[4] = *(const float4*)&Bs[kk][64 + tx * 4];
#pragma unroll
            for (int i = 0; i < 8; i++)
#pragma unroll
                for (int j = 0; j < 8; j++)
                    acc[i][j] += a[i] * b[j];
        }
        __syncthreads();
    }

#pragma unroll
    for (int i = 0; i < 8; i++) {
        int row = blockIdx.y * GBM + ((i < 4) ? (ty * 4 + i) : (64 + ty * 4 + i - 4));
        float* Cr = C + (size_t)row * N + blockIdx.x * GBN;
        float4 c0 = make_float4(acc[i][0], acc[i][1], acc[i][2], acc[i][3]);
        float4 c1 = make_float4(acc[i][4], acc[i][5], acc[i][6], acc[i][7]);
        *(float4*)&Cr[tx * 4]      = c0;
        *(float4*)&Cr[64 + tx * 4] = c1;
    }
}

// ======================= RoPE (in-place, pair per thread) ===================
// X: [M_ROWS, ncols]; per head (128 cols): out1 = x1*cos - x2*sin,
//                                          out2 = x2*cos + x1*sin (x2 = col+64)
__global__ void rope_kernel(float* __restrict__ X,
                            const float* __restrict__ cosT,
                            const float* __restrict__ sinT,
                            int ncols) {
    int half = ncols >> 1;
    int idx = blockIdx.x * blockDim.x + threadIdx.x;
    int total = M_ROWS * half;
    if (idx >= total) return;
    int row = idx / half;
    int p   = idx - row * half;
    int head = p >> 6;        // p / 64
    int hd   = p & 63;        // p % 64
    int t    = row & (T_SEQ - 1);   // row % T  (B*T rows, T power of 2)
    int c1 = head * HEAD_DIM + hd;
    int c2 = c1 + 64;
    size_t base = (size_t)row * ncols;
    float x1 = X[base + c1];
    float x2 = X[base + c2];
    float cv1 = cosT[t * HEAD_DIM + hd];
    float sv1 = sinT[t * HEAD_DIM + hd];
    float cv2 = cosT[t * HEAD_DIM + hd + 64];
    float sv2 = sinT[t * HEAD_DIM + hd + 64];
    X[base + c1] = x1 * cv1 - x2 * sv1;
    X[base + c2] = x2 * cv2 + x1 * sv2;
}

// ======================= Flash attention (causal, fp32) =====================
// Q: [B*T, D_MODEL] (head h at col h*128), K/V: [B*T, KV_D], O: [B*T, D_MODEL]
#define BQ 64
#define BKV 64
#define QST 129   // padded row stride for Q/K/V tiles
#define PST 65    // padded row stride for P tile

#define FLASH_SMEM_FLOATS (3 * BKV * QST + BQ * PST)

__global__ __launch_bounds__(256)
void flash_kernel(const float* __restrict__ Q, const float* __restrict__ K,
                  const float* __restrict__ V, float* __restrict__ O) {
    extern __shared__ float sm[];
    float* Qs = sm;                    // [BQ][QST]
    float* Ks = Qs + BQ * QST;         // [BKV][QST]
    float* Vs = Ks + BKV * QST;        // [BKV][QST]
    float* Ps = Vs + BKV * QST;        // [BQ][PST]

    int b = blockIdx.z;
    int h = blockIdx.y;
    int q0 = blockIdx.x * BQ;
    int kvh = h / GRP;
    int tid = threadIdx.x;
    int tx = tid & 15, ty = tid >> 4;

    const float scale = 0.08838834764831845f;   // 1/sqrt(128)

    // Load Q tile, prescaled
    const float* Qg = Q + ((size_t)(b * T_SEQ + q0)) * D_MODEL + h * HEAD_DIM;
    for (int idx = tid; idx < BQ * HEAD_DIM; idx += 256) {
        int r = idx >> 7, c = idx & 127;
        Qs[r * QST + c] = Qg[(size_t)r * D_MODEL + c] * scale;
    }

    float m_prev[4], l[4], o[4][8];
#pragma unroll
    for (int i = 0; i < 4; i++) {
        m_prev[i] = -INFINITY;
        l[i] = 0.f;
#pragma unroll
        for (int j = 0; j < 8; j++) o[i][j] = 0.f;
    }

    int ntiles = q0 / BKV + 1;
    for (int t = 0; t < ntiles; t++) {
        int kv0 = t * BKV;
        __syncthreads();   // previous PV done (and Q load visible on t==0)

        const float* Kg = K + ((size_t)(b * T_SEQ + kv0)) * KV_D + kvh * HEAD_DIM;
        const float* Vg = V + ((size_t)(b * T_SEQ + kv0)) * KV_D + kvh * HEAD_DIM;
        for (int idx = tid; idx < BKV * HEAD_DIM; idx += 256) {
            int r = idx >> 7, c = idx & 127;
            Ks[r * QST + c] = Kg[(size_t)r * KV_D + c];
            Vs[r * QST + c] = Vg[(size_t)r * KV_D + c];
        }
        __syncthreads();

        // S = Q * K^T  (4x4 micro-tile per thread)
        float s[4][4];
#pragma unroll
        for (int i = 0; i < 4; i++)
#pragma unroll
            for (int j = 0; j < 4; j++) s[i][j] = 0.f;

#pragma unroll 8
        for (int k = 0; k < HEAD_DIM; k++) {
            float a[4], bb[4];
#pragma unroll
            for (int i = 0; i < 4; i++) a[i] = Qs[(ty * 4 + i) * QST + k];
#pragma unroll
            for (int j = 0; j < 4; j++) bb[j] = Ks[(tx * 4 + j) * QST + k];
#pragma unroll
            for (int i = 0; i < 4; i++)
#pragma unroll
                for (int j = 0; j < 4; j++)
                    s[i][j] += a[i] * bb[j];
        }

        // causal mask (only the diagonal tile can have masked entries)
        if (t == ntiles - 1) {
#pragma unroll
            for (int i = 0; i < 4; i++) {
                int row = q0 + ty * 4 + i;
#pragma unroll
                for (int j = 0; j < 4; j++) {
                    int col = kv0 + tx * 4 + j;
                    if (col > row) s[i][j] = -INFINITY;
                }
            }
        }

        // online softmax per row (reduce across 16 tx lanes, width-16 shfl)
#pragma unroll
        for (int i = 0; i < 4; i++) {
            float mt = fmaxf(fmaxf(s[i][0], s[i][1]), fmaxf(s[i][2], s[i][3]));
#pragma unroll
            for (int off = 8; off >= 1; off >>= 1)
                mt = fmaxf(mt, __shfl_xor_sync(0xffffffffu, mt, off, 16));
            float mnew = fmaxf(m_prev[i], mt);
            float corr = __expf(m_prev[i] - mnew);
            float lt = 0.f;
#pragma unroll
            for (int j = 0; j < 4; j++) {
                float p = __expf(s[i][j] - mnew);
                s[i][j] = p;
                lt += p;
            }
#pragma unroll
            for (int off = 8; off >= 1; off >>= 1)
                lt += __shfl_xor_sync(0xffffffffu, lt, off, 16);
            l[i] = l[i] * corr + lt;
            m_prev[i] = mnew;
#pragma unroll
            for (int j = 0; j < 8; j++) o[i][j] *= corr;
#pragma unroll
            for (int j = 0; j < 4; j++)
                Ps[(ty * 4 + i) * PST + tx * 4 + j] = s[i][j];
        }
        __syncthreads();

        // O += P * V   (4 rows x 8 cols per thread)
#pragma unroll 8
        for (int k = 0; k < BKV; k++) {
            float p[4], v[8];
#pragma unroll
            for (int i = 0; i < 4; i++) p[i] = Ps[(ty * 4 + i) * PST + k];
#pragma unroll
            for (int j = 0; j < 8; j++) v[j] = Vs[k * QST + tx * 8 + j];
#pragma unroll
            for (int i = 0; i < 4; i++)
#pragma unroll
                for (int j = 0; j < 8; j++)
                    o[i][j] += p[i] * v[j];
        }
    }

    // epilogue: normalize and store
    float* Og = O + ((size_t)(b * T_SEQ + q0)) * D_MODEL + h * HEAD_DIM;
#pragma unroll
    for (int i = 0; i < 4; i++) {
        float inv = 1.f / l[i];
#pragma unroll
        for (int j = 0; j < 8; j++)
            Og[(size_t)(ty * 4 + i) * D_MODEL + tx * 8 + j] = o[i][j] * inv;
    }
}

// ======================= launch =============================================
// NOTE: no static state anywhere ("no static guards" rule). Both runtime API
// calls below are non-stream ops: safe (and uncaptured) under graph capture,
// idempotent across calls, deterministic.
extern "C" void kernel_launch(void* const* d_in, const int* in_sizes, int n_in,
                              void* d_out, int out_size) {
    const float* x    = (const float*)d_in[0];
    const float* cosT = (const float*)d_in[1];
    const float* sinT = (const float*)d_in[2];
    const float* Wq   = (const float*)d_in[3];
    const float* Wk   = (const float*)d_in[4];
    const float* Wv   = (const float*)d_in[5];
    const float* Wo   = (const float*)d_in[6];
    float* out        = (float*)d_out;

    void* p = nullptr;
    cudaGetSymbolAddress(&p, g_scratch);
    float* base = (float*)p;
    float* q  = base + OFF_Q;
    float* k  = base + OFF_K;
    float* v  = base + OFF_V;
    float* at = base + OFF_ATTN;

    cudaFuncSetAttribute(flash_kernel,
                         cudaFuncAttributeMaxDynamicSharedMemorySize,
                         (int)(FLASH_SMEM_FLOATS * sizeof(float)));

    // Projections: C = X * W^T
    gemm_nt<<<dim3(D_MODEL / GBN, M_ROWS / GBM), 256>>>(x, Wq, q, D_MODEL, D_MODEL);
    gemm_nt<<<dim3(KV_D / GBN,    M_ROWS / GBM), 256>>>(x, Wk, k, KV_D,    D_MODEL);
    gemm_nt<<<dim3(KV_D / GBN,    M_ROWS / GBM), 256>>>(x, Wv, v, KV_D,    D_MODEL);

    // RoPE in place
    {
        int totq = M_ROWS * (D_MODEL / 2);
        rope_kernel<<<(totq + 255) / 256, 256>>>(q, cosT, sinT, D_MODEL);
        int totk = M_ROWS * (KV_D / 2);
        rope_kernel<<<(totk + 255) / 256, 256>>>(k, cosT, sinT, KV_D);
    }

    // Flash attention
    {
        size_t smem = FLASH_SMEM_FLOATS * sizeof(float);
        dim3 grid(T_SEQ / BQ, N_HEADS, 2);
        flash_kernel<<<grid, 256, smem>>>(q, k, v, at);
    }

    // Output projection
    gemm_nt<<<dim3(D_MODEL / GBN, M_ROWS / GBM), 256>>>(at, Wo, out, D_MODEL, D_MODEL);
}

// round 5
// speedup vs baseline: 1.4691x; 1.4691x over previous
#include <cuda_runtime.h>
#include <math.h>
#include <stdint.h>

// Problem constants
#define M_ROWS   4096     // B*T
#define T_SEQ    2048
#define D_MODEL  2048
#define KV_D     512
#define HEAD_DIM 128
#define N_HEADS  16
#define N_KV     4
#define GRP      4        // H / HKV

// ---------------- scratch (one device global; no allocations allowed) ------
#define OFF_Q    0
#define OFF_K    (M_ROWS * D_MODEL)
#define OFF_V    (OFF_K + M_ROWS * KV_D)
#define OFF_ATTN (OFF_V + M_ROWS * KV_D)
#define SCRATCH_FLOATS (OFF_ATTN + M_ROWS * D_MODEL)
__device__ float g_scratch[SCRATCH_FLOATS];

// ======================= TF32 tensor-core NT GEMM ==========================
// C[M,N] = A[M,K] * B[N,K]^T ; A,B row-major K-contiguous.
// Tile 128x128x16. 256 threads = 8 warps, warp grid 2(m) x 4(n),
// each warp: 64x32 = 4 x 4 tiles of mma.m16n8k8 (tf32, fp32 accum).
#define GBM 128
#define GBN 128
#define GBK 16
#define SST 20    // smem row stride (floats): conflict-free & float4-aligned

__device__ __forceinline__ uint32_t f2tf32(float f) {
    uint32_t r;
    asm("cvt.rna.tf32.f32 %0, %1;" : "=r"(r) : "f"(f));
    return r;
}

__device__ __forceinline__ void mma_tf32(float* d, const uint32_t* a, const uint32_t* b) {
    asm volatile(
        "mma.sync.aligned.m16n8k8.row.col.f32.tf32.tf32.f32 "
        "{%0,%1,%2,%3}, {%4,%5,%6,%7}, {%8,%9}, {%0,%1,%2,%3};"
        : "+f"(d[0]), "+f"(d[1]), "+f"(d[2]), "+f"(d[3])
        : "r"(a[0]), "r"(a[1]), "r"(a[2]), "r"(a[3]), "r"(b[0]), "r"(b[1]));
}

__global__ __launch_bounds__(256)
void gemm_nt_tf32(const float* __restrict__ A, const float* __restrict__ B,
                  float* __restrict__ C, int N, int K) {
    __shared__ uint32_t As[GBM][SST];
    __shared__ uint32_t Bs[GBN][SST];

    int tid  = threadIdx.x;
    int lane = tid & 31;
    int warp = tid >> 5;
    int wm = warp & 1;            // 0..1  -> 64-row slab
    int wn = warp >> 1;           // 0..3  -> 32-col slab
    int grp = lane >> 2;          // 0..7
    int qid = lane & 3;           // 0..3

    const float* Ab = A + (size_t)blockIdx.y * GBM * K;
    const float* Bb = B + (size_t)blockIdx.x * GBN * K;

    int lr = tid >> 1;            // 0..127 : tile row
    int lk = (tid & 1) * 8;       // 0 or 8 : k offset

    float acc[4][4][4];
#pragma unroll
    for (int i = 0; i < 4; i++)
#pragma unroll
        for (int j = 0; j < 4; j++)
#pragma unroll
            for (int r = 0; r < 4; r++) acc[i][j][r] = 0.f;

    // prefetch first tile
    float4 pa0 = *(const float4*)(Ab + (size_t)lr * K + lk);
    float4 pa1 = *(const float4*)(Ab + (size_t)lr * K + lk + 4);
    float4 pb0 = *(const float4*)(Bb + (size_t)lr * K + lk);
    float4 pb1 = *(const float4*)(Bb + (size_t)lr * K + lk + 4);

    for (int k0 = 0; k0 < K; k0 += GBK) {
        // store (tf32-rounded) current tile
        As[lr][lk + 0] = f2tf32(pa0.x); As[lr][lk + 1] = f2tf32(pa0.y);
        As[lr][lk + 2] = f2tf32(pa0.z); As[lr][lk + 3] = f2tf32(pa0.w);
        As[lr][lk + 4] = f2tf32(pa1.x); As[lr][lk + 5] = f2tf32(pa1.y);
        As[lr][lk + 6] = f2tf32(pa1.z); As[lr][lk + 7] = f2tf32(pa1.w);
        Bs[lr][lk + 0] = f2tf32(pb0.x); Bs[lr][lk + 1] = f2tf32(pb0.y);
        Bs[lr][lk + 2] = f2tf32(pb0.z); Bs[lr][lk + 3] = f2tf32(pb0.w);
        Bs[lr][lk + 4] = f2tf32(pb1.x); Bs[lr][lk + 5] = f2tf32(pb1.y);
        Bs[lr][lk + 6] = f2tf32(pb1.z); Bs[lr][lk + 7] = f2tf32(pb1.w);
        __syncthreads();

        // prefetch next tile
        if (k0 + GBK < K) {
            pa0 = *(const float4*)(Ab + (size_t)lr * K + k0 + GBK + lk);
            pa1 = *(const float4*)(Ab + (size_t)lr * K + k0 + GBK + lk + 4);
            pb0 = *(const float4*)(Bb + (size_t)lr * K + k0 + GBK + lk);
            pb1 = *(const float4*)(Bb + (size_t)lr * K + k0 + GBK + lk + 4);
        }

#pragma unroll
        for (int ks = 0; ks < 2; ks++) {
            int kb = ks * 8;
            uint32_t af[4][4];
#pragma unroll
            for (int mt = 0; mt < 4; mt++) {
                int r0 = wm * 64 + mt * 16 + grp;
                af[mt][0] = As[r0][kb + qid];
                af[mt][1] = As[r0 + 8][kb + qid];
                af[mt][2] = As[r0][kb + qid + 4];
                af[mt][3] = As[r0 + 8][kb + qid + 4];
            }
            uint32_t bf[4][2];
#pragma unroll
            for (int nt = 0; nt < 4; nt++) {
                int c0 = wn * 32 + nt * 8 + grp;
                bf[nt][0] = Bs[c0][kb + qid];
                bf[nt][1] = Bs[c0][kb + qid + 4];
            }
#pragma unroll
            for (int mt = 0; mt < 4; mt++)
#pragma unroll
                for (int nt = 0; nt < 4; nt++)
                    mma_tf32(acc[mt][nt], af[mt], bf[nt]);
        }
        __syncthreads();
    }

    // epilogue
#pragma unroll
    for (int mt = 0; mt < 4; mt++) {
        int row0 = blockIdx.y * GBM + wm * 64 + mt * 16 + grp;
#pragma unroll
        for (int nt = 0; nt < 4; nt++) {
            int col = blockIdx.x * GBN + wn * 32 + nt * 8 + qid * 2;
            *(float2*)&C[(size_t)row0 * N + col] =
                make_float2(acc[mt][nt][0], acc[mt][nt][1]);
            *(float2*)&C[(size_t)(row0 + 8) * N + col] =
                make_float2(acc[mt][nt][2], acc[mt][nt][3]);
        }
    }
}

// ======================= RoPE (in-place, pair per thread) ===================
__global__ void rope_kernel(float* __restrict__ X,
                            const float* __restrict__ cosT,
                            const float* __restrict__ sinT,
                            int ncols) {
    int half = ncols >> 1;
    int idx = blockIdx.x * blockDim.x + threadIdx.x;
    int total = M_ROWS * half;
    if (idx >= total) return;
    int row = idx / half;
    int p   = idx - row * half;
    int head = p >> 6;
    int hd   = p & 63;
    int t    = row & (T_SEQ - 1);
    int c1 = head * HEAD_DIM + hd;
    int c2 = c1 + 64;
    size_t base = (size_t)row * ncols;
    float x1 = X[base + c1];
    float x2 = X[base + c2];
    float cv1 = cosT[t * HEAD_DIM + hd];
    float sv1 = sinT[t * HEAD_DIM + hd];
    float cv2 = cosT[t * HEAD_DIM + hd + 64];
    float sv2 = sinT[t * HEAD_DIM + hd + 64];
    X[base + c1] = x1 * cv1 - x2 * sv1;
    X[base + c2] = x2 * cv2 + x1 * sv2;
}

// ======================= Flash attention (causal, fp32) =====================
#define BQ 64
#define BKV 64
#define QST 129
#define PST 65
#define FLASH_SMEM_FLOATS (3 * BKV * QST + BQ * PST)

__global__ __launch_bounds__(256)
void flash_kernel(const float* __restrict__ Q, const float* __restrict__ K,
                  const float* __restrict__ V, float* __restrict__ O) {
    extern __shared__ float sm[];
    float* Qs = sm;
    float* Ks = Qs + BQ * QST;
    float* Vs = Ks + BKV * QST;
    float* Ps = Vs + BKV * QST;

    int b = blockIdx.z;
    int h = blockIdx.y;
    int q0 = blockIdx.x * BQ;
    int kvh = h / GRP;
    int tid = threadIdx.x;
    int tx = tid & 15, ty = tid >> 4;

    const float scale = 0.08838834764831845f;

    const float* Qg = Q + ((size_t)(b * T_SEQ + q0)) * D_MODEL + h * HEAD_DIM;
    for (int idx = tid; idx < BQ * HEAD_DIM; idx += 256) {
        int r = idx >> 7, c = idx & 127;
        Qs[r * QST + c] = Qg[(size_t)r * D_MODEL + c] * scale;
    }

    float m_prev[4], l[4], o[4][8];
#pragma unroll
    for (int i = 0; i < 4; i++) {
        m_prev[i] = -INFINITY;
        l[i] = 0.f;
#pragma unroll
        for (int j = 0; j < 8; j++) o[i][j] = 0.f;
    }

    int ntiles = q0 / BKV + 1;
    for (int t = 0; t < ntiles; t++) {
        int kv0 = t * BKV;
        __syncthreads();

        const float* Kg = K + ((size_t)(b * T_SEQ + kv0)) * KV_D + kvh * HEAD_DIM;
        const float* Vg = V + ((size_t)(b * T_SEQ + kv0)) * KV_D + kvh * HEAD_DIM;
        for (int idx = tid; idx < BKV * HEAD_DIM; idx += 256) {
            int r = idx >> 7, c = idx & 127;
            Ks[r * QST + c] = Kg[(size_t)r * KV_D + c];
            Vs[r * QST + c] = Vg[(size_t)r * KV_D + c];
        }
        __syncthreads();

        float s[4][4];
#pragma unroll
        for (int i = 0; i < 4; i++)
#pragma unroll
            for (int j = 0; j < 4; j++) s[i][j] = 0.f;

#pragma unroll 8
        for (int k = 0; k < HEAD_DIM; k++) {
            float a[4], bb[4];
#pragma unroll
            for (int i = 0; i < 4; i++) a[i] = Qs[(ty * 4 + i) * QST + k];
#pragma unroll
            for (int j = 0; j < 4; j++) bb[j] = Ks[(tx * 4 + j) * QST + k];
#pragma unroll
            for (int i = 0; i < 4; i++)
#pragma unroll
                for (int j = 0; j < 4; j++)
                    s[i][j] += a[i] * bb[j];
        }

        if (t == ntiles - 1) {
#pragma unroll
            for (int i = 0; i < 4; i++) {
                int row = q0 + ty * 4 + i;
#pragma unroll
                for (int j = 0; j < 4; j++) {
                    int col = kv0 + tx * 4 + j;
                    if (col > row) s[i][j] = -INFINITY;
                }
            }
        }

#pragma unroll
        for (int i = 0; i < 4; i++) {
            float mt = fmaxf(fmaxf(s[i][0], s[i][1]), fmaxf(s[i][2], s[i][3]));
#pragma unroll
            for (int off = 8; off >= 1; off >>= 1)
                mt = fmaxf(mt, __shfl_xor_sync(0xffffffffu, mt, off, 16));
            float mnew = fmaxf(m_prev[i], mt);
            float corr = __expf(m_prev[i] - mnew);
            float lt = 0.f;
#pragma unroll
            for (int j = 0; j < 4; j++) {
                float p = __expf(s[i][j] - mnew);
                s[i][j] = p;
                lt += p;
            }
#pragma unroll
            for (int off = 8; off >= 1; off >>= 1)
                lt += __shfl_xor_sync(0xffffffffu, lt, off, 16);
            l[i] = l[i] * corr + lt;
            m_prev[i] = mnew;
#pragma unroll
            for (int j = 0; j < 8; j++) o[i][j] *= corr;
#pragma unroll
            for (int j = 0; j < 4; j++)
                Ps[(ty * 4 + i) * PST + tx * 4 + j] = s[i][j];
        }
        __syncthreads();

#pragma unroll 8
        for (int k = 0; k < BKV; k++) {
            float p[4], v[8];
#pragma unroll
            for (int i = 0; i < 4; i++) p[i] = Ps[(ty * 4 + i) * PST + k];
#pragma unroll
            for (int j = 0; j < 8; j++) v[j] = Vs[k * QST + tx * 8 + j];
#pragma unroll
            for (int i = 0; i < 4; i++)
#pragma unroll
                for (int j = 0; j < 8; j++)
                    o[i][j] += p[i] * v[j];
        }
    }

    float* Og = O + ((size_t)(b * T_SEQ + q0)) * D_MODEL + h * HEAD_DIM;
#pragma unroll
    for (int i = 0; i < 4; i++) {
        float inv = 1.f / l[i];
#pragma unroll
        for (int j = 0; j < 8; j++)
            Og[(size_t)(ty * 4 + i) * D_MODEL + tx * 8 + j] = o[i][j] * inv;
    }
}

// ======================= launch =============================================
extern "C" void kernel_launch(void* const* d_in, const int* in_sizes, int n_in,
                              void* d_out, int out_size) {
    const float* x    = (const float*)d_in[0];
    const float* cosT = (const float*)d_in[1];
    const float* sinT = (const float*)d_in[2];
    const float* Wq   = (const float*)d_in[3];
    const float* Wk   = (const float*)d_in[4];
    const float* Wv   = (const float*)d_in[5];
    const float* Wo   = (const float*)d_in[6];
    float* out        = (float*)d_out;

    void* p = nullptr;
    cudaGetSymbolAddress(&p, g_scratch);
    float* base = (float*)p;
    float* q  = base + OFF_Q;
    float* k  = base + OFF_K;
    float* v  = base + OFF_V;
    float* at = base + OFF_ATTN;

    cudaFuncSetAttribute(flash_kernel,
                         cudaFuncAttributeMaxDynamicSharedMemorySize,
                         (int)(FLASH_SMEM_FLOATS * sizeof(float)));

    // Projections: C = X * W^T  (TF32 tensor cores)
    gemm_nt_tf32<<<dim3(D_MODEL / GBN, M_ROWS / GBM), 256>>>(x, Wq, q, D_MODEL, D_MODEL);
    gemm_nt_tf32<<<dim3(KV_D / GBN,    M_ROWS / GBM), 256>>>(x, Wk, k, KV_D,    D_MODEL);
    gemm_nt_tf32<<<dim3(KV_D / GBN,    M_ROWS / GBM), 256>>>(x, Wv, v, KV_D,    D_MODEL);

    // RoPE in place
    {
        int totq = M_ROWS * (D_MODEL / 2);
        rope_kernel<<<(totq + 255) / 256, 256>>>(q, cosT, sinT, D_MODEL);
        int totk = M_ROWS * (KV_D / 2);
        rope_kernel<<<(totk + 255) / 256, 256>>>(k, cosT, sinT, KV_D);
    }

    // Flash attention
    {
        size_t smem = FLASH_SMEM_FLOATS * sizeof(float);
        dim3 grid(T_SEQ / BQ, N_HEADS, 2);
        flash_kernel<<<grid, 256, smem>>>(q, k, v, at);
    }

    // Output projection
    gemm_nt_tf32<<<dim3(D_MODEL / GBN, M_ROWS / GBM), 256>>>(at, Wo, out, D_MODEL, D_MODEL);
}